// round 1
// baseline (speedup 1.0000x reference)
#include <cuda_runtime.h>
#include <cuda_bf16.h>
#include <math.h>

// Problem constants (fixed by the dataset: B=4096, D=1024)
#define BDIM 4096
#define DDIM 1024
#define INV_T 20.0f          // 1 / 0.05
#define NBLK 32              // BDIM / 128 block-columns

// Deterministic scratch (no atomics anywhere -> bitwise-stable output)
__device__ float g_img_sq[BDIM];
__device__ float g_txt_sq[BDIM];
__device__ float g_diag[BDIM];
__device__ float g_part[BDIM][NBLK];   // per-(row, block-col) partial row sums

// ---------------------------------------------------------------------------
// Kernel 1: squared norms of each row. grid = (BDIM, 2); y==0 -> image, y==1 -> text
// ---------------------------------------------------------------------------
__global__ void norms_kernel(const float* __restrict__ img,
                             const float* __restrict__ txt) {
    const int row = blockIdx.x;
    const int tid = threadIdx.x;              // 256 threads
    const float* base = (blockIdx.y == 0) ? img : txt;
    const float4* p = reinterpret_cast<const float4*>(base + (size_t)row * DDIM);

    float s = 0.0f;
    for (int c = tid; c < DDIM / 4; c += 256) {
        float4 v = p[c];
        s += v.x * v.x + v.y * v.y + v.z * v.z + v.w * v.w;
    }
    // warp reduce
    #pragma unroll
    for (int m = 16; m > 0; m >>= 1) s += __shfl_xor_sync(0xffffffffu, s, m);

    __shared__ float red[8];
    if ((tid & 31) == 0) red[tid >> 5] = s;
    __syncthreads();
    if (tid == 0) {
        float t = 0.0f;
        #pragma unroll
        for (int w = 0; w < 8; w++) t += red[w];
        if (blockIdx.y == 0) g_img_sq[row] = t;
        else                 g_txt_sq[row] = t;
    }
}

// ---------------------------------------------------------------------------
// Kernel 2: fused GEMM + epilogue.
//   C[i][j] = dot(image_i, text_j)   (A = image, B = text, both K-major)
//   sim     = exp(-sqrt(max(isq+tsq-2C,0)) / T)
//   g_part[i][bj] = sum over this block's 128 columns of sim
//   g_diag[i]     = sim on the diagonal
// Block tile 128x128, K-tile 16, 256 threads, 8x8 per thread.
// ---------------------------------------------------------------------------
__global__ __launch_bounds__(256, 2)
void gemm_sim_kernel(const float* __restrict__ A,    // image  [BDIM][DDIM]
                     const float* __restrict__ Bm) { // text   [BDIM][DDIM]
    __shared__ float As[16][128];
    __shared__ float Bs[16][128];

    const int bj   = blockIdx.x;
    const int bi   = blockIdx.y;
    const int row0 = bi * 128;
    const int col0 = bj * 128;

    const int tid = threadIdx.x;         // 0..255
    const int tx  = tid & 15;            // column group
    const int ty  = tid >> 4;            // row group

    float acc[8][8];
    #pragma unroll
    for (int r = 0; r < 8; r++)
        #pragma unroll
        for (int c = 0; c < 8; c++) acc[r][c] = 0.0f;

    for (int kt = 0; kt < DDIM; kt += 16) {
        // Cooperative load: 128 rows x 16 k = 512 float4 per operand, 2 per thread
        #pragma unroll
        for (int l = 0; l < 2; ++l) {
            const int f  = tid + l * 256;      // 0..511
            const int r  = f >> 2;             // row within tile
            const int kq = (f & 3) * 4;        // k quad

            float4 va = *reinterpret_cast<const float4*>(
                A + (size_t)(row0 + r) * DDIM + kt + kq);
            As[kq + 0][r] = va.x; As[kq + 1][r] = va.y;
            As[kq + 2][r] = va.z; As[kq + 3][r] = va.w;

            float4 vb = *reinterpret_cast<const float4*>(
                Bm + (size_t)(col0 + r) * DDIM + kt + kq);
            Bs[kq + 0][r] = vb.x; Bs[kq + 1][r] = vb.y;
            Bs[kq + 2][r] = vb.z; Bs[kq + 3][r] = vb.w;
        }
        __syncthreads();

        #pragma unroll
        for (int k = 0; k < 16; ++k) {
            float a[8], b[8];
            float4 a0 = *reinterpret_cast<const float4*>(&As[k][ty * 8]);
            float4 a1 = *reinterpret_cast<const float4*>(&As[k][ty * 8 + 4]);
            float4 b0 = *reinterpret_cast<const float4*>(&Bs[k][tx * 8]);
            float4 b1 = *reinterpret_cast<const float4*>(&Bs[k][tx * 8 + 4]);
            a[0]=a0.x; a[1]=a0.y; a[2]=a0.z; a[3]=a0.w;
            a[4]=a1.x; a[5]=a1.y; a[6]=a1.z; a[7]=a1.w;
            b[0]=b0.x; b[1]=b0.y; b[2]=b0.z; b[3]=b0.w;
            b[4]=b1.x; b[5]=b1.y; b[6]=b1.z; b[7]=b1.w;
            #pragma unroll
            for (int r = 0; r < 8; r++)
                #pragma unroll
                for (int c = 0; c < 8; c++)
                    acc[r][c] = fmaf(a[r], b[c], acc[r][c]);
        }
        __syncthreads();
    }

    // Epilogue: distances -> sim -> per-row partial sums + diagonal
    float isq[8], tsq[8];
    #pragma unroll
    for (int r = 0; r < 8; r++) isq[r] = g_img_sq[row0 + ty * 8 + r];
    #pragma unroll
    for (int c = 0; c < 8; c++) tsq[c] = g_txt_sq[col0 + tx * 8 + c];

    float rowpart[8];
    #pragma unroll
    for (int r = 0; r < 8; r++) {
        const int gi = row0 + ty * 8 + r;
        float rs = 0.0f;
        #pragma unroll
        for (int c = 0; c < 8; c++) {
            const int gj = col0 + tx * 8 + c;
            float sq  = isq[r] + tsq[c] - 2.0f * acc[r][c];
            float d   = sqrtf(fmaxf(sq, 0.0f));
            float sim = __expf(-d * INV_T);
            rs += sim;
            if (gi == gj) g_diag[gi] = sim;
        }
        rowpart[r] = rs;
    }

    // Reduce across the 16 tx lanes that share the same 8 rows.
    // Warp layout: lanes 0..15 have one ty, lanes 16..31 the next -> xor masks
    // 1,2,4,8 stay within each 16-lane half.
    #pragma unroll
    for (int m = 1; m < 16; m <<= 1)
        #pragma unroll
        for (int r = 0; r < 8; r++)
            rowpart[r] += __shfl_xor_sync(0xffffffffu, rowpart[r], m);

    if (tx == 0) {
        #pragma unroll
        for (int r = 0; r < 8; r++)
            g_part[row0 + ty * 8 + r][bj] = rowpart[r];
    }
}

// ---------------------------------------------------------------------------
// Kernel 3: final loss. loss = (1/B) * sum_i -log(num_i / (rowsum_i - num_i))
// ---------------------------------------------------------------------------
__global__ void loss_kernel(float* __restrict__ out) {
    const int tid = threadIdx.x;   // 256 threads, 1 block
    float s = 0.0f;
    for (int i = tid; i < BDIM; i += 256) {
        float rowsum = 0.0f;
        #pragma unroll
        for (int b = 0; b < NBLK; b++) rowsum += g_part[i][b];
        float num = g_diag[i];
        float den = rowsum - num;
        s += (den != 0.0f) ? (logf(den) - logf(num)) : 0.0f;
    }
    #pragma unroll
    for (int m = 16; m > 0; m >>= 1) s += __shfl_xor_sync(0xffffffffu, s, m);

    __shared__ float red[8];
    if ((tid & 31) == 0) red[tid >> 5] = s;
    __syncthreads();
    if (tid == 0) {
        float t = 0.0f;
        #pragma unroll
        for (int w = 0; w < 8; w++) t += red[w];
        out[0] = t / (float)BDIM;
    }
}

// ---------------------------------------------------------------------------
// Launch. Inputs per metadata order: d_in[0] = text_embeddings,
// d_in[1] = image_embeddings. Output: 1 float.
// ---------------------------------------------------------------------------
extern "C" void kernel_launch(void* const* d_in, const int* in_sizes, int n_in,
                              void* d_out, int out_size) {
    const float* txt = (const float*)d_in[0];
    const float* img = (const float*)d_in[1];
    float* out = (float*)d_out;

    dim3 ngrid(BDIM, 2);
    norms_kernel<<<ngrid, 256>>>(img, txt);

    dim3 ggrid(NBLK, NBLK);
    gemm_sim_kernel<<<ggrid, 256>>>(img, txt);

    loss_kernel<<<1, 256>>>(out);
}

// round 2
// speedup vs baseline: 4.7075x; 4.7075x over previous
#include <cuda_runtime.h>
#include <cuda_bf16.h>
#include <math.h>
#include <stdint.h>

// Problem constants (fixed: B=4096, D=1024)
#define BDIM 4096
#define DDIM 1024
#define INV_T 20.0f          // 1 / 0.05
#define NBLK 32              // BDIM / 128 block-columns
#define KT 32                // k elements per smem tile
#define RS 40                // padded bf16 row stride in smem (80B: (5r+c)%8 conflict-free)

// Deterministic scratch (no atomics -> bitwise-stable output)
__device__ float g_img_sq[BDIM];
__device__ float g_txt_sq[BDIM];
__device__ float g_diag[BDIM];
__device__ float g_part[BDIM][NBLK];
__device__ __nv_bfloat16 g_Abf[(size_t)BDIM * DDIM];   // image, bf16
__device__ __nv_bfloat16 g_Bbf[(size_t)BDIM * DDIM];   // text,  bf16

// ---------------------------------------------------------------------------
// Kernel 1: fp32 -> bf16 convert + squared norms (norms stay fp32-accurate).
// grid = (BDIM, 2); y==0 -> image, y==1 -> text. 256 threads, 1 float4 each.
// ---------------------------------------------------------------------------
__global__ void convert_norms_kernel(const float* __restrict__ img,
                                     const float* __restrict__ txt) {
    const int row = blockIdx.x;
    const int tid = threadIdx.x;   // 0..255, DDIM/4 == 256
    const float* src = (blockIdx.y == 0) ? img : txt;
    __nv_bfloat16* dst = (blockIdx.y == 0) ? g_Abf : g_Bbf;

    float4 v = reinterpret_cast<const float4*>(src + (size_t)row * DDIM)[tid];
    float s = v.x * v.x + v.y * v.y + v.z * v.z + v.w * v.w;

    __nv_bfloat162* d2 = reinterpret_cast<__nv_bfloat162*>(
        dst + (size_t)row * DDIM + tid * 4);
    d2[0] = __floats2bfloat162_rn(v.x, v.y);
    d2[1] = __floats2bfloat162_rn(v.z, v.w);

    #pragma unroll
    for (int m = 16; m > 0; m >>= 1) s += __shfl_xor_sync(0xffffffffu, s, m);
    __shared__ float red[8];
    if ((tid & 31) == 0) red[tid >> 5] = s;
    __syncthreads();
    if (tid == 0) {
        float t = 0.0f;
        #pragma unroll
        for (int w = 0; w < 8; w++) t += red[w];
        if (blockIdx.y == 0) g_img_sq[row] = t;
        else                 g_txt_sq[row] = t;
    }
}

// ---------------------------------------------------------------------------
// Kernel 2: bf16 tensor-core GEMM (mma.sync m16n8k16) + fused epilogue.
// Block 128x128, 8 warps in 2(m) x 4(n), warp tile 64x32, 2-stage cp.async.
// ---------------------------------------------------------------------------
__device__ __forceinline__ float simf(float sq) {
    return __expf(-INV_T * sqrtf(fmaxf(sq, 0.0f)));
}

__global__ __launch_bounds__(256, 2)
void mma_sim_kernel() {
    __shared__ __nv_bfloat16 As[2][128 * RS];
    __shared__ __nv_bfloat16 Bs[2][128 * RS];
    __shared__ float s_isq[128];
    __shared__ float s_tsq[128];
    __shared__ float red[128][4];

    const int bj = blockIdx.x;
    const int bi = blockIdx.y;
    const int row0 = bi * 128;
    const int col0 = bj * 128;

    const int tid  = threadIdx.x;
    const int lane = tid & 31;
    const int warp = tid >> 5;
    const int wm   = warp >> 2;   // 0..1
    const int wn   = warp & 3;    // 0..3

    if (tid < 128) s_isq[tid] = g_img_sq[row0 + tid];
    else           s_tsq[tid - 128] = g_txt_sq[col0 + tid - 128];

    float acc[4][4][4];
    #pragma unroll
    for (int mf = 0; mf < 4; mf++)
        #pragma unroll
        for (int nf = 0; nf < 4; nf++)
            #pragma unroll
            for (int r = 0; r < 4; r++) acc[mf][nf][r] = 0.0f;

    // ---- async tile loader: 128 rows x 4 chunks x 16B per operand ----
    #define LOAD_STAGE(s, kt)                                                  \
    do {                                                                       \
        _Pragma("unroll")                                                      \
        for (int l = 0; l < 2; l++) {                                          \
            int id = tid + l * 256;                                            \
            int r  = id >> 2;                                                  \
            int c  = id & 3;                                                   \
            uint32_t da = (uint32_t)__cvta_generic_to_shared(                  \
                &As[s][r * RS + c * 8]);                                       \
            const __nv_bfloat16* sa =                                          \
                g_Abf + (size_t)(row0 + r) * DDIM + (kt) + c * 8;              \
            asm volatile("cp.async.cg.shared.global [%0], [%1], 16;\n"         \
                         :: "r"(da), "l"(sa));                                 \
            uint32_t db = (uint32_t)__cvta_generic_to_shared(                  \
                &Bs[s][r * RS + c * 8]);                                       \
            const __nv_bfloat16* sb =                                          \
                g_Bbf + (size_t)(col0 + r) * DDIM + (kt) + c * 8;              \
            asm volatile("cp.async.cg.shared.global [%0], [%1], 16;\n"         \
                         :: "r"(db), "l"(sb));                                 \
        }                                                                      \
        asm volatile("cp.async.commit_group;\n");                              \
    } while (0)

    LOAD_STAGE(0, 0);

    const int NK = DDIM / KT;   // 32 k-tiles
    for (int it = 0; it < NK; it++) {
        if (it + 1 < NK) {
            LOAD_STAGE((it + 1) & 1, (it + 1) * KT);
            asm volatile("cp.async.wait_group 1;\n");
        } else {
            asm volatile("cp.async.wait_group 0;\n");
        }
        __syncthreads();

        const __nv_bfloat16* as = As[it & 1];
        const __nv_bfloat16* bs = Bs[it & 1];

        #pragma unroll
        for (int ks = 0; ks < 2; ks++) {
            const int k0 = ks * 16;
            uint32_t a[4][4], b[2][4];

            #pragma unroll
            for (int mf = 0; mf < 4; mf++) {
                int r    = wm * 64 + mf * 16 + (lane & 15);
                int koff = k0 + ((lane >> 4) << 3);
                uint32_t addr = (uint32_t)__cvta_generic_to_shared(
                    &as[r * RS + koff]);
                asm volatile(
                    "ldmatrix.sync.aligned.m8n8.x4.shared.b16 "
                    "{%0,%1,%2,%3}, [%4];\n"
                    : "=r"(a[mf][0]), "=r"(a[mf][1]),
                      "=r"(a[mf][2]), "=r"(a[mf][3])
                    : "r"(addr));
            }
            #pragma unroll
            for (int p = 0; p < 2; p++) {
                int n    = wn * 32 + p * 16 + ((lane >> 4) << 3) + (lane & 7);
                int koff = k0 + (((lane >> 3) & 1) << 3);
                uint32_t addr = (uint32_t)__cvta_generic_to_shared(
                    &bs[n * RS + koff]);
                asm volatile(
                    "ldmatrix.sync.aligned.m8n8.x4.shared.b16 "
                    "{%0,%1,%2,%3}, [%4];\n"
                    : "=r"(b[p][0]), "=r"(b[p][1]),
                      "=r"(b[p][2]), "=r"(b[p][3])
                    : "r"(addr));
            }
            #pragma unroll
            for (int mf = 0; mf < 4; mf++) {
                #pragma unroll
                for (int nf = 0; nf < 4; nf++) {
                    uint32_t b0 = b[nf >> 1][(nf & 1) * 2];
                    uint32_t b1 = b[nf >> 1][(nf & 1) * 2 + 1];
                    asm volatile(
                        "mma.sync.aligned.m16n8k16.row.col.f32.bf16.bf16.f32 "
                        "{%0,%1,%2,%3},{%4,%5,%6,%7},{%8,%9},{%0,%1,%2,%3};\n"
                        : "+f"(acc[mf][nf][0]), "+f"(acc[mf][nf][1]),
                          "+f"(acc[mf][nf][2]), "+f"(acc[mf][nf][3])
                        : "r"(a[mf][0]), "r"(a[mf][1]),
                          "r"(a[mf][2]), "r"(a[mf][3]),
                          "r"(b0), "r"(b1));
                }
            }
        }
        __syncthreads();
    }
    #undef LOAD_STAGE

    // ---- fused epilogue: sim -> row partial sums + diagonal ----
    const bool diagblk = (bi == bj);
    #pragma unroll
    for (int mf = 0; mf < 4; mf++) {
        const int r_lo = wm * 64 + mf * 16 + (lane >> 2);  // tile row
        const int r_hi = r_lo + 8;
        const float ia = s_isq[r_lo];
        const float ib = s_isq[r_hi];
        float s_lo = 0.0f, s_hi = 0.0f;

        #pragma unroll
        for (int nf = 0; nf < 4; nf++) {
            const int c0 = wn * 32 + nf * 8 + (lane & 3) * 2;  // tile col
            const float t0 = s_tsq[c0];
            const float t1 = s_tsq[c0 + 1];
            float e00 = simf(ia + t0 - 2.0f * acc[mf][nf][0]);
            float e01 = simf(ia + t1 - 2.0f * acc[mf][nf][1]);
            float e10 = simf(ib + t0 - 2.0f * acc[mf][nf][2]);
            float e11 = simf(ib + t1 - 2.0f * acc[mf][nf][3]);
            s_lo += e00 + e01;
            s_hi += e10 + e11;
            if (diagblk) {
                if (r_lo == c0)     g_diag[row0 + r_lo] = e00;
                if (r_lo == c0 + 1) g_diag[row0 + r_lo] = e01;
                if (r_hi == c0)     g_diag[row0 + r_hi] = e10;
                if (r_hi == c0 + 1) g_diag[row0 + r_hi] = e11;
            }
        }
        // reduce across the 4 lanes (lane&3) sharing each row
        s_lo += __shfl_xor_sync(0xffffffffu, s_lo, 1);
        s_lo += __shfl_xor_sync(0xffffffffu, s_lo, 2);
        s_hi += __shfl_xor_sync(0xffffffffu, s_hi, 1);
        s_hi += __shfl_xor_sync(0xffffffffu, s_hi, 2);
        if ((lane & 3) == 0) {
            red[r_lo][wn] = s_lo;
            red[r_hi][wn] = s_hi;
        }
    }
    __syncthreads();
    if (tid < 128) {
        float rs = red[tid][0] + red[tid][1] + red[tid][2] + red[tid][3];
        g_part[row0 + tid][bj] = rs;
    }
}

// ---------------------------------------------------------------------------
// Kernel 3: final loss = (1/B) * sum_i [log(rowsum_i - num_i) - log(num_i)]
// ---------------------------------------------------------------------------
__global__ void loss_kernel(float* __restrict__ out) {
    const int tid = threadIdx.x;   // 256 threads, 1 block
    float s = 0.0f;
    for (int i = tid; i < BDIM; i += 256) {
        float rowsum = 0.0f;
        #pragma unroll
        for (int b = 0; b < NBLK; b++) rowsum += g_part[i][b];
        float num = g_diag[i];
        float den = rowsum - num;
        s += (den != 0.0f) ? (logf(den) - logf(num)) : 0.0f;
    }
    #pragma unroll
    for (int m = 16; m > 0; m >>= 1) s += __shfl_xor_sync(0xffffffffu, s, m);
    __shared__ float red[8];
    if ((tid & 31) == 0) red[tid >> 5] = s;
    __syncthreads();
    if (tid == 0) {
        float t = 0.0f;
        #pragma unroll
        for (int w = 0; w < 8; w++) t += red[w];
        out[0] = t / (float)BDIM;
    }
}

// ---------------------------------------------------------------------------
// Launch. Inputs: d_in[0] = text_embeddings, d_in[1] = image_embeddings.
// ---------------------------------------------------------------------------
extern "C" void kernel_launch(void* const* d_in, const int* in_sizes, int n_in,
                              void* d_out, int out_size) {
    const float* txt = (const float*)d_in[0];
    const float* img = (const float*)d_in[1];
    float* out = (float*)d_out;

    dim3 cgrid(BDIM, 2);
    convert_norms_kernel<<<cgrid, 256>>>(img, txt);

    dim3 ggrid(NBLK, NBLK);
    mma_sim_kernel<<<ggrid, 256>>>();

    loss_kernel<<<1, 256>>>(out);
}

// round 4
// speedup vs baseline: 4.8077x; 1.0213x over previous
#include <cuda_runtime.h>
#include <cuda_bf16.h>
#include <math.h>
#include <stdint.h>

// Problem constants (fixed: B=4096, D=1024)
#define BDIM 4096
#define DDIM 1024
#define INV_T 20.0f
#define NBLK 32                 // BDIM / 128 block-columns
#define KT 32                   // k elements per stage
#define NK (DDIM / KT)          // 32 k-tiles
#define RS 40                   // padded bf16 row stride in smem (80 B)
#define NSTG 4                  // pipeline stages
#define STG_ELEMS (128 * RS)    // bf16 elements per operand per stage
#define STG_BYTES (2 * STG_ELEMS * 2)        // A+B, bytes per stage (20480)
#define DSMEM (NSTG * STG_BYTES)             // 81920 B dynamic smem

// Deterministic scratch (no atomics -> bitwise-stable output)
__device__ float g_img_sq[BDIM];
__device__ float g_txt_sq[BDIM];
__device__ float g_diag[BDIM];
__device__ float g_part[BDIM][NBLK];
__device__ __nv_bfloat16 g_Abf[(size_t)BDIM * DDIM];   // image, bf16
__device__ __nv_bfloat16 g_Bbf[(size_t)BDIM * DDIM];   // text,  bf16

// ---------------------------------------------------------------------------
// Kernel 1: fp32 -> bf16 convert + fp32 squared norms. Warp-per-row.
// grid = (BDIM/8, 2), 256 threads. y==0 -> image, y==1 -> text.
// ---------------------------------------------------------------------------
__global__ void convert_norms_kernel(const float* __restrict__ img,
                                     const float* __restrict__ txt) {
    const int warp = threadIdx.x >> 5, lane = threadIdx.x & 31;
    const int row  = blockIdx.x * 8 + warp;
    const float* src;
    __nv_bfloat16* dst;
    float* nrm;
    if (blockIdx.y == 0) { src = img; dst = g_Abf; nrm = g_img_sq; }
    else                 { src = txt; dst = g_Bbf; nrm = g_txt_sq; }

    const float4* p = reinterpret_cast<const float4*>(src + (size_t)row * DDIM);
    __nv_bfloat162* q = reinterpret_cast<__nv_bfloat162*>(dst + (size_t)row * DDIM);

    float s = 0.0f;
    #pragma unroll
    for (int i = 0; i < 8; i++) {
        int f = i * 32 + lane;
        float4 v = p[f];
        s += v.x * v.x + v.y * v.y + v.z * v.z + v.w * v.w;
        q[f * 2]     = __floats2bfloat162_rn(v.x, v.y);
        q[f * 2 + 1] = __floats2bfloat162_rn(v.z, v.w);
    }
    #pragma unroll
    for (int m = 16; m > 0; m >>= 1) s += __shfl_xor_sync(0xffffffffu, s, m);
    if (lane == 0) nrm[row] = s;
}

// ---------------------------------------------------------------------------
// Kernel 2: bf16 mma.sync GEMM, 128x128 tile, 4-stage cp.async pipeline,
// one __syncthreads per k-tile, fused sim epilogue.
// ---------------------------------------------------------------------------
__device__ __forceinline__ float simf(float sq) {
    return __expf(-INV_T * sqrtf(fmaxf(sq, 0.0f)));
}

__device__ __forceinline__ void load_stage(__nv_bfloat16* smem, int stage,
                                           int kt, int row0, int col0, int tid) {
    __nv_bfloat16* as = smem + (size_t)stage * 2 * STG_ELEMS;
    __nv_bfloat16* bs = as + STG_ELEMS;
    #pragma unroll
    for (int l = 0; l < 2; l++) {
        const int id = tid + l * 256;      // 0..511
        const int r  = id >> 2;            // tile row 0..127
        const int c  = id & 3;             // 16B chunk 0..3 (32 k = 4 chunks)
        uint32_t da = (uint32_t)__cvta_generic_to_shared(&as[r * RS + c * 8]);
        const void* ga = g_Abf + (size_t)(row0 + r) * DDIM + kt + c * 8;
        asm volatile("cp.async.cg.shared.global [%0], [%1], 16;\n"
                     :: "r"(da), "l"(ga));
        uint32_t db = (uint32_t)__cvta_generic_to_shared(&bs[r * RS + c * 8]);
        const void* gb = g_Bbf + (size_t)(col0 + r) * DDIM + kt + c * 8;
        asm volatile("cp.async.cg.shared.global [%0], [%1], 16;\n"
                     :: "r"(db), "l"(gb));
    }
    asm volatile("cp.async.commit_group;\n" ::: "memory");
}

__global__ __launch_bounds__(256, 2)
void mma_sim_kernel() {
    extern __shared__ __nv_bfloat16 smem[];
    __shared__ float s_isq[128];
    __shared__ float s_tsq[128];
    __shared__ float red[128][4];

    const int bj = blockIdx.x;
    const int bi = blockIdx.y;
    const int row0 = bi * 128;
    const int col0 = bj * 128;

    const int tid  = threadIdx.x;
    const int lane = tid & 31;
    const int warp = tid >> 5;
    const int wm   = warp >> 2;   // 0..1 (m)
    const int wn   = warp & 3;    // 0..3 (n)

    if (tid < 128) s_isq[tid] = g_img_sq[row0 + tid];
    else           s_tsq[tid - 128] = g_txt_sq[col0 + tid - 128];

    float acc[4][4][4];
    #pragma unroll
    for (int mf = 0; mf < 4; mf++)
        #pragma unroll
        for (int nf = 0; nf < 4; nf++)
            #pragma unroll
            for (int r = 0; r < 4; r++) acc[mf][nf][r] = 0.0f;

    // Prologue: fill 3 of 4 stages
    load_stage(smem, 0, 0, row0, col0, tid);
    load_stage(smem, 1, KT, row0, col0, tid);
    load_stage(smem, 2, 2 * KT, row0, col0, tid);

    for (int it = 0; it < NK; it++) {
        asm volatile("cp.async.wait_group 2;\n" ::: "memory");
        __syncthreads();

        // Issue loads for stage it+3 (overwrites buffer read at iter it-1;
        // all reads of it-1 completed before the barrier above).
        if (it + 3 < NK)
            load_stage(smem, (it + 3) & 3, (it + 3) * KT, row0, col0, tid);
        else
            asm volatile("cp.async.commit_group;\n" ::: "memory");

        const __nv_bfloat16* as = smem + (size_t)(it & 3) * 2 * STG_ELEMS;
        const __nv_bfloat16* bs = as + STG_ELEMS;

        #pragma unroll
        for (int ks = 0; ks < 2; ks++) {
            const int k0 = ks * 16;
            uint32_t a[4][4], b[2][4];

            #pragma unroll
            for (int mf = 0; mf < 4; mf++) {
                int r    = wm * 64 + mf * 16 + (lane & 15);
                int koff = k0 + ((lane >> 4) << 3);
                uint32_t addr = (uint32_t)__cvta_generic_to_shared(
                    &as[r * RS + koff]);
                asm volatile(
                    "ldmatrix.sync.aligned.m8n8.x4.shared.b16 "
                    "{%0,%1,%2,%3}, [%4];\n"
                    : "=r"(a[mf][0]), "=r"(a[mf][1]),
                      "=r"(a[mf][2]), "=r"(a[mf][3])
                    : "r"(addr));
            }
            #pragma unroll
            for (int p = 0; p < 2; p++) {
                int n    = wn * 32 + p * 16 + ((lane >> 4) << 3) + (lane & 7);
                int koff = k0 + (((lane >> 3) & 1) << 3);
                uint32_t addr = (uint32_t)__cvta_generic_to_shared(
                    &bs[n * RS + koff]);
                asm volatile(
                    "ldmatrix.sync.aligned.m8n8.x4.shared.b16 "
                    "{%0,%1,%2,%3}, [%4];\n"
                    : "=r"(b[p][0]), "=r"(b[p][1]),
                      "=r"(b[p][2]), "=r"(b[p][3])
                    : "r"(addr));
            }
            #pragma unroll
            for (int mf = 0; mf < 4; mf++) {
                #pragma unroll
                for (int nf = 0; nf < 4; nf++) {
                    uint32_t b0 = b[nf >> 1][(nf & 1) * 2];
                    uint32_t b1 = b[nf >> 1][(nf & 1) * 2 + 1];
                    asm volatile(
                        "mma.sync.aligned.m16n8k16.row.col.f32.bf16.bf16.f32 "
                        "{%0,%1,%2,%3},{%4,%5,%6,%7},{%8,%9},{%0,%1,%2,%3};\n"
                        : "+f"(acc[mf][nf][0]), "+f"(acc[mf][nf][1]),
                          "+f"(acc[mf][nf][2]), "+f"(acc[mf][nf][3])
                        : "r"(a[mf][0]), "r"(a[mf][1]),
                          "r"(a[mf][2]), "r"(a[mf][3]),
                          "r"(b0), "r"(b1));
                }
            }
        }
    }

    // ---- fused epilogue: sim -> row partial sums + diagonal ----
    const bool diagblk = (bi == bj);
    #pragma unroll
    for (int mf = 0; mf < 4; mf++) {
        const int r_lo = wm * 64 + mf * 16 + (lane >> 2);
        const int r_hi = r_lo + 8;
        const float ia = s_isq[r_lo];
        const float ib = s_isq[r_hi];
        float s_lo = 0.0f, s_hi = 0.0f;

        #pragma unroll
        for (int nf = 0; nf < 4; nf++) {
            const int c0 = wn * 32 + nf * 8 + (lane & 3) * 2;
            const float t0 = s_tsq[c0];
            const float t1 = s_tsq[c0 + 1];
            float e00 = simf(ia + t0 - 2.0f * acc[mf][nf][0]);
            float e01 = simf(ia + t1 - 2.0f * acc[mf][nf][1]);
            float e10 = simf(ib + t0 - 2.0f * acc[mf][nf][2]);
            float e11 = simf(ib + t1 - 2.0f * acc[mf][nf][3]);
            s_lo += e00 + e01;
            s_hi += e10 + e11;
            if (diagblk) {
                if (r_lo == c0)     g_diag[row0 + r_lo] = e00;
                if (r_lo == c0 + 1) g_diag[row0 + r_lo] = e01;
                if (r_hi == c0)     g_diag[row0 + r_hi] = e10;
                if (r_hi == c0 + 1) g_diag[row0 + r_hi] = e11;
            }
        }
        s_lo += __shfl_xor_sync(0xffffffffu, s_lo, 1);
        s_lo += __shfl_xor_sync(0xffffffffu, s_lo, 2);
        s_hi += __shfl_xor_sync(0xffffffffu, s_hi, 1);
        s_hi += __shfl_xor_sync(0xffffffffu, s_hi, 2);
        if ((lane & 3) == 0) {
            red[r_lo][wn] = s_lo;
            red[r_hi][wn] = s_hi;
        }
    }
    __syncthreads();
    if (tid < 128) {
        g_part[row0 + tid][bj] = red[tid][0] + red[tid][1]
                               + red[tid][2] + red[tid][3];
    }
}

// ---------------------------------------------------------------------------
// Kernel 3: final loss = (1/B) * sum_i [log(rowsum_i - num_i) - log(num_i)]
// ---------------------------------------------------------------------------
__global__ void loss_kernel(float* __restrict__ out) {
    const int tid = threadIdx.x;
    float s = 0.0f;
    for (int i = tid; i < BDIM; i += 256) {
        float rowsum = 0.0f;
        #pragma unroll
        for (int b = 0; b < NBLK; b++) rowsum += g_part[i][b];
        float num = g_diag[i];
        float den = rowsum - num;
        s += (den != 0.0f) ? (logf(den) - logf(num)) : 0.0f;
    }
    #pragma unroll
    for (int m = 16; m > 0; m >>= 1) s += __shfl_xor_sync(0xffffffffu, s, m);
    __shared__ float red[8];
    if ((tid & 31) == 0) red[tid >> 5] = s;
    __syncthreads();
    if (tid == 0) {
        float t = 0.0f;
        #pragma unroll
        for (int w = 0; w < 8; w++) t += red[w];
        out[0] = t / (float)BDIM;
    }
}

// ---------------------------------------------------------------------------
// Launch. Inputs: d_in[0] = text_embeddings, d_in[1] = image_embeddings.
// ---------------------------------------------------------------------------
extern "C" void kernel_launch(void* const* d_in, const int* in_sizes, int n_in,
                              void* d_out, int out_size) {
    const float* txt = (const float*)d_in[0];
    const float* img = (const float*)d_in[1];
    float* out = (float*)d_out;

    cudaFuncSetAttribute(mma_sim_kernel,
                         cudaFuncAttributeMaxDynamicSharedMemorySize, DSMEM);

    dim3 cgrid(BDIM / 8, 2);
    convert_norms_kernel<<<cgrid, 256>>>(img, txt);

    dim3 ggrid(NBLK, NBLK);
    mma_sim_kernel<<<ggrid, 256, DSMEM>>>();

    loss_kernel<<<1, 256>>>(out);
}

// round 5
// speedup vs baseline: 5.0170x; 1.0435x over previous
#include <cuda_runtime.h>
#include <cuda_bf16.h>
#include <math.h>
#include <stdint.h>

// Problem constants (fixed: B=4096, D=1024)
#define BDIM 4096
#define DDIM 1024
#define INV_T 20.0f
#define NBLK 32                 // BDIM / 128 block-columns
#define KT 64                   // fp8 k elements per stage (64 B rows)
#define NK (DDIM / KT)          // 16 k-tiles
#define RSB 80                  // padded fp8 row stride in bytes (conflict-free)
#define NSTG 4                  // pipeline stages
#define STG_BYTES (2 * 128 * RSB)            // A+B per stage = 20480 B
#define DSMEM (NSTG * STG_BYTES)             // 81920 B dynamic smem
#define INV_S2 (1.0f / 8192.0f)              // 2 / (128*128)

// Deterministic scratch (no atomics -> bitwise-stable output)
__device__ float g_img_sq[BDIM];
__device__ float g_txt_sq[BDIM];
__device__ float g_diag[BDIM];
__device__ float g_part[BDIM][NBLK];
__device__ uint8_t g_A8[(size_t)BDIM * DDIM];   // image, e4m3 (x128)
__device__ uint8_t g_B8[(size_t)BDIM * DDIM];   // text,  e4m3 (x128)

// ---------------------------------------------------------------------------
// Kernel 1: fp32 -> e4m3 (scaled by 128) + fp32 exact squared norms.
// Warp-per-row. grid = (BDIM/8, 2), 256 threads. y==0 -> image, y==1 -> text.
// ---------------------------------------------------------------------------
__device__ __forceinline__ uint16_t f2_to_e4m3x2(float hi, float lo) {
    // d.byte0 = e4m3(lo), d.byte1 = e4m3(hi)
    uint16_t d;
    asm("cvt.rn.satfinite.e4m3x2.f32 %0, %1, %2;" : "=h"(d) : "f"(hi), "f"(lo));
    return d;
}

__global__ void convert_norms_kernel(const float* __restrict__ img,
                                     const float* __restrict__ txt) {
    const int warp = threadIdx.x >> 5, lane = threadIdx.x & 31;
    const int row  = blockIdx.x * 8 + warp;
    const float* src;
    uint8_t* dst;
    float* nrm;
    if (blockIdx.y == 0) { src = img; dst = g_A8; nrm = g_img_sq; }
    else                 { src = txt; dst = g_B8; nrm = g_txt_sq; }

    const float4* p = reinterpret_cast<const float4*>(src + (size_t)row * DDIM);
    uint32_t* q = reinterpret_cast<uint32_t*>(dst + (size_t)row * DDIM);

    float s = 0.0f;
    #pragma unroll
    for (int i = 0; i < 8; i++) {
        int f = i * 32 + lane;            // float4 index 0..255
        float4 v = p[f];
        s += v.x * v.x + v.y * v.y + v.z * v.z + v.w * v.w;
        uint16_t lo = f2_to_e4m3x2(v.y * 128.0f, v.x * 128.0f); // bytes x,y
        uint16_t hi = f2_to_e4m3x2(v.w * 128.0f, v.z * 128.0f); // bytes z,w
        q[f] = (uint32_t)lo | ((uint32_t)hi << 16);
    }
    #pragma unroll
    for (int m = 16; m > 0; m >>= 1) s += __shfl_xor_sync(0xffffffffu, s, m);
    if (lane == 0) nrm[row] = s;
}

// ---------------------------------------------------------------------------
// Kernel 2: e4m3 mma.sync m16n8k32 GEMM, 128x128 tile, 4-stage cp.async
// pipeline, fused sim epilogue.
// ---------------------------------------------------------------------------
__device__ __forceinline__ void load_stage(uint8_t* smem, int stage,
                                           int kt, int row0, int col0, int tid) {
    uint8_t* as = smem + (size_t)stage * STG_BYTES;
    uint8_t* bs = as + 128 * RSB;
    #pragma unroll
    for (int l = 0; l < 2; l++) {
        const int id = tid + l * 256;      // 0..511
        const int r  = id >> 2;            // tile row 0..127
        const int c  = id & 3;             // 16B chunk 0..3 (64 fp8 = 4 chunks)
        uint32_t da = (uint32_t)__cvta_generic_to_shared(&as[r * RSB + c * 16]);
        const void* ga = g_A8 + (size_t)(row0 + r) * DDIM + kt + c * 16;
        asm volatile("cp.async.cg.shared.global [%0], [%1], 16;\n"
                     :: "r"(da), "l"(ga));
        uint32_t db = (uint32_t)__cvta_generic_to_shared(&bs[r * RSB + c * 16]);
        const void* gb = g_B8 + (size_t)(col0 + r) * DDIM + kt + c * 16;
        asm volatile("cp.async.cg.shared.global [%0], [%1], 16;\n"
                     :: "r"(db), "l"(gb));
    }
    asm volatile("cp.async.commit_group;\n" ::: "memory");
}

__global__ __launch_bounds__(256, 2)
void mma_sim_kernel() {
    extern __shared__ uint8_t smem[];
    __shared__ float s_isq[128];
    __shared__ float s_tsq[128];
    __shared__ float red[128][4];

    const int bj = blockIdx.x;
    const int bi = blockIdx.y;
    const int row0 = bi * 128;
    const int col0 = bj * 128;

    const int tid  = threadIdx.x;
    const int lane = tid & 31;
    const int warp = tid >> 5;
    const int wm   = warp >> 2;   // 0..1 (m)
    const int wn   = warp & 3;    // 0..3 (n)

    if (tid < 128) s_isq[tid] = g_img_sq[row0 + tid];
    else           s_tsq[tid - 128] = g_txt_sq[col0 + tid - 128];

    float acc[4][4][4];
    #pragma unroll
    for (int mf = 0; mf < 4; mf++)
        #pragma unroll
        for (int nf = 0; nf < 4; nf++)
            #pragma unroll
            for (int r = 0; r < 4; r++) acc[mf][nf][r] = 0.0f;

    // Prologue: fill 3 of 4 stages
    load_stage(smem, 0, 0, row0, col0, tid);
    load_stage(smem, 1, KT, row0, col0, tid);
    load_stage(smem, 2, 2 * KT, row0, col0, tid);

    for (int it = 0; it < NK; it++) {
        asm volatile("cp.async.wait_group 2;\n" ::: "memory");
        __syncthreads();

        if (it + 3 < NK)
            load_stage(smem, (it + 3) & 3, (it + 3) * KT, row0, col0, tid);
        else
            asm volatile("cp.async.commit_group;\n" ::: "memory");

        const uint8_t* as = smem + (size_t)(it & 3) * STG_BYTES;
        const uint8_t* bs = as + 128 * RSB;

        #pragma unroll
        for (int ks = 0; ks < 2; ks++) {      // two k32 steps per 64-fp8 stage
            const int kb = ks * 32;           // byte offset of this k-step
            uint32_t a[4][4], b[2][4];

            #pragma unroll
            for (int mf = 0; mf < 4; mf++) {
                int r     = wm * 64 + mf * 16 + (lane & 15);
                int koffb = kb + ((lane >> 4) << 4);   // +16B for upper half
                uint32_t addr = (uint32_t)__cvta_generic_to_shared(
                    &as[r * RSB + koffb]);
                asm volatile(
                    "ldmatrix.sync.aligned.m8n8.x4.shared.b16 "
                    "{%0,%1,%2,%3}, [%4];\n"
                    : "=r"(a[mf][0]), "=r"(a[mf][1]),
                      "=r"(a[mf][2]), "=r"(a[mf][3])
                    : "r"(addr));
            }
            #pragma unroll
            for (int p = 0; p < 2; p++) {
                int n     = wn * 32 + p * 16 + ((lane >> 4) << 3) + (lane & 7);
                int koffb = kb + (((lane >> 3) & 1) << 4);
                uint32_t addr = (uint32_t)__cvta_generic_to_shared(
                    &bs[n * RSB + koffb]);
                asm volatile(
                    "ldmatrix.sync.aligned.m8n8.x4.shared.b16 "
                    "{%0,%1,%2,%3}, [%4];\n"
                    : "=r"(b[p][0]), "=r"(b[p][1]),
                      "=r"(b[p][2]), "=r"(b[p][3])
                    : "r"(addr));
            }
            #pragma unroll
            for (int mf = 0; mf < 4; mf++) {
                #pragma unroll
                for (int nf = 0; nf < 4; nf++) {
                    uint32_t b0 = b[nf >> 1][(nf & 1) * 2];
                    uint32_t b1 = b[nf >> 1][(nf & 1) * 2 + 1];
                    asm volatile(
                        "mma.sync.aligned.m16n8k32.row.col.f32.e4m3.e4m3.f32 "
                        "{%0,%1,%2,%3},{%4,%5,%6,%7},{%8,%9},{%0,%1,%2,%3};\n"
                        : "+f"(acc[mf][nf][0]), "+f"(acc[mf][nf][1]),
                          "+f"(acc[mf][nf][2]), "+f"(acc[mf][nf][3])
                        : "r"(a[mf][0]), "r"(a[mf][1]),
                          "r"(a[mf][2]), "r"(a[mf][3]),
                          "r"(b0), "r"(b1));
                }
            }
        }
    }

    // ---- fused epilogue: sim -> row partial sums + diagonal ----
    // sq = isq + tsq - acc * (2/S^2);  S = 128
    const bool diagblk = (bi == bj);
    #pragma unroll
    for (int mf = 0; mf < 4; mf++) {
        const int r_lo = wm * 64 + mf * 16 + (lane >> 2);
        const int r_hi = r_lo + 8;
        const float ia = s_isq[r_lo];
        const float ib = s_isq[r_hi];
        float s_lo = 0.0f, s_hi = 0.0f;

        #pragma unroll
        for (int nf = 0; nf < 4; nf++) {
            const int c0 = wn * 32 + nf * 8 + (lane & 3) * 2;
            const float t0 = s_tsq[c0];
            const float t1 = s_tsq[c0 + 1];
            float q00 = fmaf(acc[mf][nf][0], -INV_S2, ia + t0);
            float q01 = fmaf(acc[mf][nf][1], -INV_S2, ia + t1);
            float q10 = fmaf(acc[mf][nf][2], -INV_S2, ib + t0);
            float q11 = fmaf(acc[mf][nf][3], -INV_S2, ib + t1);
            float e00 = __expf(-INV_T * sqrtf(fmaxf(q00, 0.0f)));
            float e01 = __expf(-INV_T * sqrtf(fmaxf(q01, 0.0f)));
            float e10 = __expf(-INV_T * sqrtf(fmaxf(q10, 0.0f)));
            float e11 = __expf(-INV_T * sqrtf(fmaxf(q11, 0.0f)));
            s_lo += e00 + e01;
            s_hi += e10 + e11;
            if (diagblk) {
                if (r_lo == c0)     g_diag[row0 + r_lo] = e00;
                if (r_lo == c0 + 1) g_diag[row0 + r_lo] = e01;
                if (r_hi == c0)     g_diag[row0 + r_hi] = e10;
                if (r_hi == c0 + 1) g_diag[row0 + r_hi] = e11;
            }
        }
        s_lo += __shfl_xor_sync(0xffffffffu, s_lo, 1);
        s_lo += __shfl_xor_sync(0xffffffffu, s_lo, 2);
        s_hi += __shfl_xor_sync(0xffffffffu, s_hi, 1);
        s_hi += __shfl_xor_sync(0xffffffffu, s_hi, 2);
        if ((lane & 3) == 0) {
            red[r_lo][wn] = s_lo;
            red[r_hi][wn] = s_hi;
        }
    }
    __syncthreads();
    if (tid < 128) {
        g_part[row0 + tid][bj] = red[tid][0] + red[tid][1]
                               + red[tid][2] + red[tid][3];
    }
}

// ---------------------------------------------------------------------------
// Kernel 3: final loss = (1/B) * sum_i [log(rowsum_i - num_i) - log(num_i)]
// ---------------------------------------------------------------------------
__global__ void loss_kernel(float* __restrict__ out) {
    const int tid = threadIdx.x;
    float s = 0.0f;
    for (int i = tid; i < BDIM; i += 256) {
        float rowsum = 0.0f;
        #pragma unroll
        for (int b = 0; b < NBLK; b++) rowsum += g_part[i][b];
        float num = g_diag[i];
        float den = rowsum - num;
        s += (den != 0.0f) ? (logf(den) - logf(num)) : 0.0f;
    }
    #pragma unroll
    for (int m = 16; m > 0; m >>= 1) s += __shfl_xor_sync(0xffffffffu, s, m);
    __shared__ float red[8];
    if ((tid & 31) == 0) red[tid >> 5] = s;
    __syncthreads();
    if (tid == 0) {
        float t = 0.0f;
        #pragma unroll
        for (int w = 0; w < 8; w++) t += red[w];
        out[0] = t / (float)BDIM;
    }
}

// ---------------------------------------------------------------------------
// Launch. Inputs: d_in[0] = text_embeddings, d_in[1] = image_embeddings.
// ---------------------------------------------------------------------------
extern "C" void kernel_launch(void* const* d_in, const int* in_sizes, int n_in,
                              void* d_out, int out_size) {
    const float* txt = (const float*)d_in[0];
    const float* img = (const float*)d_in[1];
    float* out = (float*)d_out;

    cudaFuncSetAttribute(mma_sim_kernel,
                         cudaFuncAttributeMaxDynamicSharedMemorySize, DSMEM);

    dim3 cgrid(BDIM / 8, 2);
    convert_norms_kernel<<<cgrid, 256>>>(img, txt);

    dim3 ggrid(NBLK, NBLK);
    mma_sim_kernel<<<ggrid, 256, DSMEM>>>();

    loss_kernel<<<1, 256>>>(out);
}